// round 1
// baseline (speedup 1.0000x reference)
#include <cuda_runtime.h>
#include <cstdint>

#define NN    20000
#define DD    32
#define HH    64
#define G4    256   // 4*H

// ---------------- scratch (static device globals; no runtime allocation) ----------------
__device__ int   g_nbr_sorted[NN * DD];
__device__ float g_P[(size_t)NN * G4];      // per-layer input projection (+ biases)
__device__ float g_agg[(size_t)NN * HH];    // LSTM final hidden per node
__device__ float g_hbufA[(size_t)NN * HH];
__device__ float g_hbufB[(size_t)NN * HH];

// ---------------- math helpers ----------------
__device__ __forceinline__ float sig_f(float x) {
    return __fdividef(1.0f, 1.0f + __expf(-x));
}
__device__ __forceinline__ float tanh_f(float x) {
    // tanh(x) = 2*sigmoid(2x) - 1 ; saturates correctly at +/-inf
    return __fdividef(2.0f, 1.0f + __expf(-2.0f * x)) - 1.0f;
}

// ---------------- 1) sort neighbors: one warp per node, bitonic-32 ----------------
__global__ void sort_nbr_kernel(const int* __restrict__ nbr) {
    int gtid = blockIdx.x * blockDim.x + threadIdx.x;
    int node = gtid >> 5;
    int lane = gtid & 31;
    if (node >= NN) return;
    int v = nbr[node * DD + lane];
#pragma unroll
    for (int k = 2; k <= 32; k <<= 1) {
#pragma unroll
        for (int j = k >> 1; j > 0; j >>= 1) {
            int p = __shfl_xor_sync(0xffffffffu, v, j);
            bool dirUp   = ((lane & k) == 0);
            bool lower   = ((lane & j) == 0);
            bool keepMin = (lower == dirUp);
            int mn = min(v, p), mx = max(v, p);
            v = keepMin ? mn : mx;
        }
    }
    g_nbr_sorted[node * DD + lane] = v;
}

// ---------------- 2) P = h_prev @ W_ih^T + (b_ih + b_hh)  [N, 256] ----------------
template <int IND>
__global__ __launch_bounds__(256) void proj_kernel(const float* __restrict__ hprev,
                                                   const float* __restrict__ W_ih,
                                                   const float* __restrict__ b_ih,
                                                   const float* __restrict__ b_hh) {
    __shared__ float hrow[16 * IND];
    const int j    = threadIdx.x;       // gate column 0..255
    const int base = blockIdx.x * 16;   // 16 nodes per block (20000/16 = 1250 blocks)

    float w[IND];
#pragma unroll
    for (int k = 0; k < IND; k++) w[k] = __ldg(&W_ih[j * IND + k]);
    float bias = __ldg(&b_ih[j]) + __ldg(&b_hh[j]);

    // rows are contiguous -> flat coalesced copy
    for (int e = j; e < 16 * IND; e += 256) hrow[e] = hprev[(size_t)base * IND + e];
    __syncthreads();

#pragma unroll
    for (int n0 = 0; n0 < 16; n0 += 4) {
        float acc[4] = {bias, bias, bias, bias};
#pragma unroll
        for (int k = 0; k < IND; k++) {
            float wv = w[k];
#pragma unroll
            for (int c = 0; c < 4; c++)
                acc[c] = fmaf(hrow[(n0 + c) * IND + k], wv, acc[c]);
        }
#pragma unroll
        for (int c = 0; c < 4; c++)
            g_P[(size_t)(base + n0 + c) * G4 + j] = acc[c];
    }
}

// ---------------- 3) LSTM over 32 sorted neighbors; 16 nodes / block ----------------
// Thread j holds W_hh row j (64 floats) in registers. gates[n][j] accumulated from
// broadcast LDS of h_sm. Cell update is distributed 4 elements/thread with c in regs.
__global__ __launch_bounds__(256, 2) void lstm_kernel(const float* __restrict__ W_hh) {
    __shared__ float h_sm[16][HH];
    __shared__ float act[16][G4];
    __shared__ int   idx_sm[16];

    const int j    = threadIdx.x;
    const int base = blockIdx.x * 16;
    const int gt   = j >> 6;            // 0:i 1:f 2:g 3:o

    float4 w4[16];
    const float4* wrow = reinterpret_cast<const float4*>(W_hh + j * HH);
#pragma unroll
    for (int k = 0; k < 16; k++) w4[k] = __ldg(wrow + k);

    for (int e = j; e < 16 * HH; e += 256) (&h_sm[0][0])[e] = 0.0f;
    float carr[4] = {0.f, 0.f, 0.f, 0.f};

    for (int t = 0; t < DD; t++) {
        if (j < 16) idx_sm[j] = g_nbr_sorted[(base + j) * DD + t];
        __syncthreads();   // h_sm(t-1) & idx ready

        // gates = P[idx] + h_sm @ W_hh^T  (thread computes column j for 16 nodes)
#pragma unroll
        for (int n0 = 0; n0 < 16; n0 += 4) {
            float a[4];
#pragma unroll
            for (int c = 0; c < 4; c++)
                a[c] = g_P[(size_t)idx_sm[n0 + c] * G4 + j];
#pragma unroll
            for (int k4 = 0; k4 < 16; k4++) {
                float4 w = w4[k4];
#pragma unroll
                for (int c = 0; c < 4; c++) {
                    float4 h = *reinterpret_cast<const float4*>(&h_sm[n0 + c][k4 * 4]);
                    a[c] = fmaf(h.x, w.x, a[c]);
                    a[c] = fmaf(h.y, w.y, a[c]);
                    a[c] = fmaf(h.z, w.z, a[c]);
                    a[c] = fmaf(h.w, w.w, a[c]);
                }
            }
#pragma unroll
            for (int c = 0; c < 4; c++) {
                float v = (gt == 2) ? tanh_f(a[c]) : sig_f(a[c]);
                act[n0 + c][j] = v;
            }
        }
        __syncthreads();   // all activated gates visible

        // cell update: 4 (node, dim) elements per thread, c kept in registers
#pragma unroll
        for (int p = 0; p < 4; p++) {
            int e = p * 256 + j;
            int n = e >> 6, d = e & 63;
            float ig = act[n][d];
            float fg = act[n][64 + d];
            float gg = act[n][128 + d];
            float og = act[n][192 + d];
            carr[p] = fmaf(fg, carr[p], ig * gg);
            h_sm[n][d] = og * tanh_f(carr[p]);
        }
        // next iteration's top __syncthreads() orders h_sm writes vs. gate reads
    }
    __syncthreads();
#pragma unroll
    for (int p = 0; p < 4; p++) {
        int e = p * 256 + j;
        int n = e >> 6, d = e & 63;
        g_agg[(size_t)(base + n) * HH + d] = h_sm[n][d];
    }
}

// ---------------- 4) h_next = relu([h_prev | agg] @ Wl^T + bl) ----------------
template <int IND>
__global__ __launch_bounds__(256) void combine_kernel(const float* __restrict__ hprev,
                                                      const float* __restrict__ Wl,
                                                      const float* __restrict__ bl,
                                                      float* __restrict__ hnext) {
    constexpr int KD    = IND + HH;
    constexpr int PITCH = KD | 1;      // odd pitch -> conflict-free column reads
    __shared__ float Wsm[HH * PITCH];
    __shared__ float xin[16][KD];

    const int t    = threadIdx.x;
    const int base = blockIdx.x * 16;

    for (int e = t; e < HH * KD; e += 256) {
        int d = e / KD, k = e - d * KD;
        Wsm[d * PITCH + k] = Wl[e];
    }
    for (int e = t; e < 16 * KD; e += 256) {
        int n = e / KD, k = e - n * KD;
        xin[n][k] = (k < IND) ? hprev[(size_t)(base + n) * IND + k]
                              : g_agg[(size_t)(base + n) * HH + (k - IND)];
    }
    __syncthreads();

    const int d = t & 63;
    int   nidx[4];
    float acc[4];
#pragma unroll
    for (int p = 0; p < 4; p++) { nidx[p] = p * 4 + (t >> 6); acc[p] = __ldg(&bl[d]); }
#pragma unroll
    for (int k = 0; k < KD; k++) {
        float wv = Wsm[d * PITCH + k];
#pragma unroll
        for (int p = 0; p < 4; p++)
            acc[p] = fmaf(xin[nidx[p]][k], wv, acc[p]);
    }
#pragma unroll
    for (int p = 0; p < 4; p++)
        hnext[(size_t)(base + nidx[p]) * HH + d] = fmaxf(acc[p], 0.0f);
}

// ---------------- 5) out[n] = h @ W_out^T + b_out ----------------
__global__ void out_kernel(const float* __restrict__ h, const float* __restrict__ Wo,
                           const float* __restrict__ bo, float* __restrict__ out) {
    int gtid = blockIdx.x * blockDim.x + threadIdx.x;
    int node = gtid >> 5;
    int lane = gtid & 31;
    if (node >= NN) return;
    const float* hr = h + (size_t)node * HH;
    float s = hr[lane] * __ldg(&Wo[lane]) + hr[32 + lane] * __ldg(&Wo[32 + lane]);
#pragma unroll
    for (int o = 16; o > 0; o >>= 1) s += __shfl_xor_sync(0xffffffffu, s, o);
    if (lane == 0) out[node] = s + __ldg(&bo[0]);
}

// ---------------- launch ----------------
extern "C" void kernel_launch(void* const* d_in, const int* in_sizes, int n_in,
                              void* d_out, int out_size) {
    const float* node_features = (const float*)d_in[0];
    const int*   nbr           = (const int*)d_in[1];
    const float* W_ih[3] = {(const float*)d_in[2],  (const float*)d_in[8],  (const float*)d_in[14]};
    const float* W_hh[3] = {(const float*)d_in[3],  (const float*)d_in[9],  (const float*)d_in[15]};
    const float* b_ih[3] = {(const float*)d_in[4],  (const float*)d_in[10], (const float*)d_in[16]};
    const float* b_hh[3] = {(const float*)d_in[5],  (const float*)d_in[11], (const float*)d_in[17]};
    const float* Wl[3]   = {(const float*)d_in[6],  (const float*)d_in[12], (const float*)d_in[18]};
    const float* bl[3]   = {(const float*)d_in[7],  (const float*)d_in[13], (const float*)d_in[19]};
    const float* W_out   = (const float*)d_in[20];
    const float* b_out   = (const float*)d_in[21];
    float* out = (float*)d_out;

    void *pA = nullptr, *pB = nullptr;
    cudaGetSymbolAddress(&pA, g_hbufA);
    cudaGetSymbolAddress(&pB, g_hbufB);
    float* hA = (float*)pA;
    float* hB = (float*)pB;

    const int NBLK = NN / 16;  // 1250

    sort_nbr_kernel<<<(NN * 32 + 255) / 256, 256>>>(nbr);

    // layer 0 : in = node_features (in_d = 3) -> hA
    proj_kernel<3><<<NBLK, 256>>>(node_features, W_ih[0], b_ih[0], b_hh[0]);
    lstm_kernel<<<NBLK, 256>>>(W_hh[0]);
    combine_kernel<3><<<NBLK, 256>>>(node_features, Wl[0], bl[0], hA);

    // layer 1 : hA -> hB
    proj_kernel<64><<<NBLK, 256>>>(hA, W_ih[1], b_ih[1], b_hh[1]);
    lstm_kernel<<<NBLK, 256>>>(W_hh[1]);
    combine_kernel<64><<<NBLK, 256>>>(hA, Wl[1], bl[1], hB);

    // layer 2 : hB -> hA
    proj_kernel<64><<<NBLK, 256>>>(hB, W_ih[2], b_ih[2], b_hh[2]);
    lstm_kernel<<<NBLK, 256>>>(W_hh[2]);
    combine_kernel<64><<<NBLK, 256>>>(hB, Wl[2], bl[2], hA);

    out_kernel<<<(NN * 32 + 255) / 256, 256>>>(hA, W_out, b_out, out);
}

// round 2
// speedup vs baseline: 1.7702x; 1.7702x over previous
#include <cuda_runtime.h>
#include <cuda_fp16.h>
#include <cstdint>

#define NN    20000
#define DD    32
#define HH    64
#define G4    256   // 4*H
#define MT    32    // nodes per lstm block
#define NBLK_LSTM (NN / MT)   // 625

// ---------------- scratch (static device globals; no runtime allocation) ----------------
__device__ int   g_nbr_sorted[NN * DD];
__device__ float g_P[(size_t)NN * G4];      // per-layer input projection (+ biases)
__device__ float g_agg[(size_t)NN * HH];    // LSTM final hidden per node
__device__ float g_hbufA[(size_t)NN * HH];
__device__ float g_hbufB[(size_t)NN * HH];

// ---------------- math helpers ----------------
__device__ __forceinline__ float sig_f(float x) {
    return __fdividef(1.0f, 1.0f + __expf(-x));
}
__device__ __forceinline__ float tanh_f(float x) {
    return __fdividef(2.0f, 1.0f + __expf(-2.0f * x)) - 1.0f;
}
__device__ __forceinline__ uint32_t pack2(float a, float b) {
    __half2 h = __floats2half2_rn(a, b);
    return *reinterpret_cast<uint32_t*>(&h);
}

// ---------------- 1) sort neighbors: one warp per node, bitonic-32 ----------------
__global__ void sort_nbr_kernel(const int* __restrict__ nbr) {
    int gtid = blockIdx.x * blockDim.x + threadIdx.x;
    int node = gtid >> 5;
    int lane = gtid & 31;
    if (node >= NN) return;
    int v = nbr[node * DD + lane];
#pragma unroll
    for (int k = 2; k <= 32; k <<= 1) {
#pragma unroll
        for (int j = k >> 1; j > 0; j >>= 1) {
            int p = __shfl_xor_sync(0xffffffffu, v, j);
            bool dirUp   = ((lane & k) == 0);
            bool lower   = ((lane & j) == 0);
            bool keepMin = (lower == dirUp);
            int mn = min(v, p), mx = max(v, p);
            v = keepMin ? mn : mx;
        }
    }
    g_nbr_sorted[node * DD + lane] = v;
}

// ---------------- 2) P = h_prev @ W_ih^T + (b_ih + b_hh)  [N, 256] ----------------
template <int IND>
__global__ __launch_bounds__(256) void proj_kernel(const float* __restrict__ hprev,
                                                   const float* __restrict__ W_ih,
                                                   const float* __restrict__ b_ih,
                                                   const float* __restrict__ b_hh) {
    __shared__ float hrow[16 * IND];
    const int j    = threadIdx.x;
    const int base = blockIdx.x * 16;

    float w[IND];
#pragma unroll
    for (int k = 0; k < IND; k++) w[k] = __ldg(&W_ih[j * IND + k]);
    float bias = __ldg(&b_ih[j]) + __ldg(&b_hh[j]);

    for (int e = j; e < 16 * IND; e += 256) hrow[e] = hprev[(size_t)base * IND + e];
    __syncthreads();

#pragma unroll
    for (int n0 = 0; n0 < 16; n0 += 4) {
        float acc[4] = {bias, bias, bias, bias};
#pragma unroll
        for (int k = 0; k < IND; k++) {
            float wv = w[k];
#pragma unroll
            for (int c = 0; c < 4; c++)
                acc[c] = fmaf(hrow[(n0 + c) * IND + k], wv, acc[c]);
        }
#pragma unroll
        for (int c = 0; c < 4; c++)
            g_P[(size_t)(base + n0 + c) * G4 + j] = acc[c];
    }
}

// ---------------- 3) LSTM via fp16 tensor-core mma ----------------
// Block: 32 nodes, 8 warps (256 thr). Warp w owns hidden dims d in [8w, 8w+8)
// for ALL FOUR gates (tiles at cols 64g+8w). Because the C-fragment thread map
// is identical across the 4 gate tiles, i/f/g/o for one (node,d) live in ONE
// thread -> cell update fully register-local. W_hh stays in registers as
// B-fragments. P[idx] is gathered straight into C-fragments (double-buffered
// one step ahead). h round-trips through 4KB swizzled smem via ldmatrix.

struct LstmSmem {
    __half h[MT][HH];   // xor-swizzled fp16 hidden state
};

// one LSTM time step (cur = accumulators preloaded with P[idx_t])
__device__ __forceinline__ void lstm_step(
    int t, int base, int w, int grp, int tig,
    char* smem_h,
    const float* __restrict__ P,
    const uint32_t (&Bfr)[4][4][2],
    const uint32_t (&lmaddr)[2][4],
    const uint32_t (&staddr)[4],
    float (&cur)[2][4][4],
    float (&nxt)[2][4][4],
    float (&cst)[2][4])
{
    __syncthreads();   // h_sm(t-1) stores visible

    // ---- ldmatrix A fragments: h(t-1) [32x64] fp16 ----
    uint32_t A[2][4][4];
#pragma unroll
    for (int m = 0; m < 2; m++)
#pragma unroll
        for (int kk = 0; kk < 4; kk++) {
            asm volatile("ldmatrix.sync.aligned.m8n8.x4.shared.b16 {%0,%1,%2,%3}, [%4];"
                         : "=r"(A[m][kk][0]), "=r"(A[m][kk][1]),
                           "=r"(A[m][kk][2]), "=r"(A[m][kk][3])
                         : "r"(lmaddr[m][kk]));
        }
    __syncthreads();   // safe to overwrite h_sm after everyone read it

    // ---- gates += h @ W_hh^T  (32 HMMA) ----
#pragma unroll
    for (int m = 0; m < 2; m++)
#pragma unroll
        for (int kk = 0; kk < 4; kk++)
#pragma unroll
            for (int g = 0; g < 4; g++) {
                asm volatile(
                    "mma.sync.aligned.m16n8k16.row.col.f32.f16.f16.f32 "
                    "{%0,%1,%2,%3}, {%4,%5,%6,%7}, {%8,%9}, {%0,%1,%2,%3};"
                    : "+f"(cur[m][g][0]), "+f"(cur[m][g][1]),
                      "+f"(cur[m][g][2]), "+f"(cur[m][g][3])
                    : "r"(A[m][kk][0]), "r"(A[m][kk][1]),
                      "r"(A[m][kk][2]), "r"(A[m][kk][3]),
                      "r"(Bfr[g][kk][0]), "r"(Bfr[g][kk][1]));
            }

    // ---- prefetch next step's P[idx] into nxt ----
    if (t < DD - 1) {
        const int col0 = 8 * w + tig * 2;
        int idxr[4];
#pragma unroll
        for (int j = 0; j < 4; j++)
            idxr[j] = g_nbr_sorted[(base + j * 8 + grp) * DD + (t + 1)];
#pragma unroll
        for (int m = 0; m < 2; m++)
#pragma unroll
            for (int g = 0; g < 4; g++) {
                float2 p0 = *reinterpret_cast<const float2*>(
                    P + (size_t)idxr[m * 2 + 0] * G4 + 64 * g + col0);
                float2 p1 = *reinterpret_cast<const float2*>(
                    P + (size_t)idxr[m * 2 + 1] * G4 + 64 * g + col0);
                nxt[m][g][0] = p0.x; nxt[m][g][1] = p0.y;
                nxt[m][g][2] = p1.x; nxt[m][g][3] = p1.y;
            }
    }

    // ---- activations + cell update (register-local) ----
    float hv[2][4];
#pragma unroll
    for (int m = 0; m < 2; m++)
#pragma unroll
        for (int e = 0; e < 4; e++) {
            float ig = sig_f (cur[m][0][e]);
            float fg = sig_f (cur[m][1][e]);
            float gg = tanh_f(cur[m][2][e]);
            float og = sig_f (cur[m][3][e]);
            float c  = fmaf(fg, cst[m][e], ig * gg);
            cst[m][e] = c;
            hv[m][e]  = og * tanh_f(c);
        }

    if (t == DD - 1) {
        // final hidden -> g_agg (fp32, [node][64])
        const int d = 8 * w + tig * 2;
#pragma unroll
        for (int m = 0; m < 2; m++)
#pragma unroll
            for (int rh = 0; rh < 2; rh++) {
                int r = m * 16 + rh * 8 + grp;
                float2 v = make_float2(hv[m][rh * 2], hv[m][rh * 2 + 1]);
                *reinterpret_cast<float2*>(&g_agg[(size_t)(base + r) * HH + d]) = v;
            }
    } else {
        // h(t) -> swizzled smem as fp16
#pragma unroll
        for (int m = 0; m < 2; m++)
#pragma unroll
            for (int rh = 0; rh < 2; rh++) {
                uint32_t v = pack2(hv[m][rh * 2], hv[m][rh * 2 + 1]);
                *reinterpret_cast<uint32_t*>(smem_h + staddr[m * 2 + rh]) = v;
            }
    }
}

__global__ __launch_bounds__(256, 1) void lstm_mma_kernel(const float* __restrict__ W_hh,
                                                          const float* __restrict__ P) {
    __shared__ LstmSmem sm;
    char* smem_h = reinterpret_cast<char*>(&sm.h[0][0]);

    const int tid  = threadIdx.x;
    const int w    = tid >> 5;
    const int lane = tid & 31;
    const int grp  = lane >> 2;   // 0..7
    const int tig  = lane & 3;    // 0..3
    const int base = blockIdx.x * MT;

    // ---- W_hh -> B fragments (resident all kernel) ----
    // gate tile g of warp w = W_hh rows [64g+8w, 64g+8w+8); col n = +grp
    uint32_t Bfr[4][4][2];
#pragma unroll
    for (int g = 0; g < 4; g++) {
        const float* row = W_hh + (size_t)(64 * g + 8 * w + grp) * HH;
#pragma unroll
        for (int kk = 0; kk < 4; kk++) {
            const float* rk = row + kk * 16 + tig * 2;
            Bfr[g][kk][0] = pack2(__ldg(rk),     __ldg(rk + 1));
            Bfr[g][kk][1] = pack2(__ldg(rk + 8), __ldg(rk + 9));
        }
    }

    // ---- precompute ldmatrix addresses (xor swizzle, invariant) ----
    // element h[r][c] stored at granule ((c>>3) ^ (r&7)), offset c&7
    uint32_t smbase = (uint32_t)__cvta_generic_to_shared(smem_h);
    uint32_t lmaddr[2][4];
    {
        int sub = lane >> 3;                       // 0..3
#pragma unroll
        for (int m = 0; m < 2; m++)
#pragma unroll
            for (int kk = 0; kk < 4; kk++) {
                int rr   = m * 16 + (lane & 7) + (sub & 1) * 8;
                int gcol = kk * 2 + (sub >> 1);
                int pc   = (gcol ^ (rr & 7)) << 3;
                lmaddr[m][kk] = smbase + (uint32_t)(rr * HH * 2 + pc * 2);
            }
    }
    // ---- precompute h-store addresses ----
    uint32_t staddr[4];
    {
        int pc = ((w ^ grp) << 3) + tig * 2;       // rr&7 == grp for all 4 rows
#pragma unroll
        for (int j = 0; j < 4; j++) {              // j = m*2+rh
            int r = (j >> 1) * 16 + (j & 1) * 8 + grp;
            staddr[j] = (uint32_t)(r * HH * 2 + pc * 2);
        }
    }

    // ---- zero h_sm ----
    for (int e = tid; e < MT * HH / 2; e += 256)
        reinterpret_cast<uint32_t*>(smem_h)[e] = 0u;

    // ---- preload step-0 gates (P[idx_0]) ----
    float bufA[2][4][4], bufB[2][4][4];
    float cst[2][4] = {{0.f,0.f,0.f,0.f},{0.f,0.f,0.f,0.f}};
    {
        const int col0 = 8 * w + tig * 2;
        int idxr[4];
#pragma unroll
        for (int j = 0; j < 4; j++)
            idxr[j] = g_nbr_sorted[(base + j * 8 + grp) * DD + 0];
#pragma unroll
        for (int m = 0; m < 2; m++)
#pragma unroll
            for (int g = 0; g < 4; g++) {
                float2 p0 = *reinterpret_cast<const float2*>(
                    P + (size_t)idxr[m * 2 + 0] * G4 + 64 * g + col0);
                float2 p1 = *reinterpret_cast<const float2*>(
                    P + (size_t)idxr[m * 2 + 1] * G4 + 64 * g + col0);
                bufA[m][g][0] = p0.x; bufA[m][g][1] = p0.y;
                bufA[m][g][2] = p1.x; bufA[m][g][3] = p1.y;
            }
    }

#pragma unroll 1
    for (int t = 0; t < DD; t += 2) {
        lstm_step(t,     base, w, grp, tig, smem_h, P, Bfr, lmaddr, staddr, bufA, bufB, cst);
        lstm_step(t + 1, base, w, grp, tig, smem_h, P, Bfr, lmaddr, staddr, bufB, bufA, cst);
    }
}

// ---------------- 4) h_next = relu([h_prev | agg] @ Wl^T + bl) ----------------
template <int IND>
__global__ __launch_bounds__(256) void combine_kernel(const float* __restrict__ hprev,
                                                      const float* __restrict__ Wl,
                                                      const float* __restrict__ bl,
                                                      float* __restrict__ hnext) {
    constexpr int KD    = IND + HH;
    constexpr int PITCH = KD | 1;
    __shared__ float Wsm[HH * PITCH];
    __shared__ float xin[16][KD];

    const int t    = threadIdx.x;
    const int base = blockIdx.x * 16;

    for (int e = t; e < HH * KD; e += 256) {
        int d = e / KD, k = e - d * KD;
        Wsm[d * PITCH + k] = Wl[e];
    }
    for (int e = t; e < 16 * KD; e += 256) {
        int n = e / KD, k = e - n * KD;
        xin[n][k] = (k < IND) ? hprev[(size_t)(base + n) * IND + k]
                              : g_agg[(size_t)(base + n) * HH + (k - IND)];
    }
    __syncthreads();

    const int d = t & 63;
    int   nidx[4];
    float acc[4];
#pragma unroll
    for (int p = 0; p < 4; p++) { nidx[p] = p * 4 + (t >> 6); acc[p] = __ldg(&bl[d]); }
#pragma unroll
    for (int k = 0; k < KD; k++) {
        float wv = Wsm[d * PITCH + k];
#pragma unroll
        for (int p = 0; p < 4; p++)
            acc[p] = fmaf(xin[nidx[p]][k], wv, acc[p]);
    }
#pragma unroll
    for (int p = 0; p < 4; p++)
        hnext[(size_t)(base + nidx[p]) * HH + d] = fmaxf(acc[p], 0.0f);
}

// ---------------- 5) out[n] = h @ W_out^T + b_out ----------------
__global__ void out_kernel(const float* __restrict__ h, const float* __restrict__ Wo,
                           const float* __restrict__ bo, float* __restrict__ out) {
    int gtid = blockIdx.x * blockDim.x + threadIdx.x;
    int node = gtid >> 5;
    int lane = gtid & 31;
    if (node >= NN) return;
    const float* hr = h + (size_t)node * HH;
    float s = hr[lane] * __ldg(&Wo[lane]) + hr[32 + lane] * __ldg(&Wo[32 + lane]);
#pragma unroll
    for (int o = 16; o > 0; o >>= 1) s += __shfl_xor_sync(0xffffffffu, s, o);
    if (lane == 0) out[node] = s + __ldg(&bo[0]);
}

// ---------------- launch ----------------
extern "C" void kernel_launch(void* const* d_in, const int* in_sizes, int n_in,
                              void* d_out, int out_size) {
    const float* node_features = (const float*)d_in[0];
    const int*   nbr           = (const int*)d_in[1];
    const float* W_ih[3] = {(const float*)d_in[2],  (const float*)d_in[8],  (const float*)d_in[14]};
    const float* W_hh[3] = {(const float*)d_in[3],  (const float*)d_in[9],  (const float*)d_in[15]};
    const float* b_ih[3] = {(const float*)d_in[4],  (const float*)d_in[10], (const float*)d_in[16]};
    const float* b_hh[3] = {(const float*)d_in[5],  (const float*)d_in[11], (const float*)d_in[17]};
    const float* Wl[3]   = {(const float*)d_in[6],  (const float*)d_in[12], (const float*)d_in[18]};
    const float* bl[3]   = {(const float*)d_in[7],  (const float*)d_in[13], (const float*)d_in[19]};
    const float* W_out   = (const float*)d_in[20];
    const float* b_out   = (const float*)d_in[21];
    float* out = (float*)d_out;

    void *pA = nullptr, *pB = nullptr, *pP = nullptr;
    cudaGetSymbolAddress(&pA, g_hbufA);
    cudaGetSymbolAddress(&pB, g_hbufB);
    cudaGetSymbolAddress(&pP, g_P);
    float* hA = (float*)pA;
    float* hB = (float*)pB;
    const float* Pp = (const float*)pP;

    const int NBLK16 = NN / 16;  // 1250

    sort_nbr_kernel<<<(NN * 32 + 255) / 256, 256>>>(nbr);

    // layer 0 : in = node_features (in_d = 3) -> hA
    proj_kernel<3><<<NBLK16, 256>>>(node_features, W_ih[0], b_ih[0], b_hh[0]);
    lstm_mma_kernel<<<NBLK_LSTM, 256>>>(W_hh[0], Pp);
    combine_kernel<3><<<NBLK16, 256>>>(node_features, Wl[0], bl[0], hA);

    // layer 1 : hA -> hB
    proj_kernel<64><<<NBLK16, 256>>>(hA, W_ih[1], b_ih[1], b_hh[1]);
    lstm_mma_kernel<<<NBLK_LSTM, 256>>>(W_hh[1], Pp);
    combine_kernel<64><<<NBLK16, 256>>>(hA, Wl[1], bl[1], hB);

    // layer 2 : hB -> hA
    proj_kernel<64><<<NBLK16, 256>>>(hB, W_ih[2], b_ih[2], b_hh[2]);
    lstm_mma_kernel<<<NBLK_LSTM, 256>>>(W_hh[2], Pp);
    combine_kernel<64><<<NBLK16, 256>>>(hB, Wl[2], bl[2], hA);

    out_kernel<<<(NN * 32 + 255) / 256, 256>>>(hA, W_out, b_out, out);
}

// round 3
// speedup vs baseline: 3.1091x; 1.7563x over previous
#include <cuda_runtime.h>
#include <cuda_fp16.h>
#include <cstdint>

#define NN    20000
#define DD    32
#define HH    64
#define G4    256   // 4*H
#define MT    32    // nodes per lstm block
#define NBLK_LSTM (NN / MT)   // 625

// dynamic smem layout for lstm kernel
#define STAGE_BYTES (2 * 8 * 256 * 16)     // 2 bufs x 8 slots x 256 tid x 16B = 65536
#define HBUF_BYTES  (2 * MT * HH * 2)      // 8192
#define LSTM_SMEM   (STAGE_BYTES + HBUF_BYTES)

// ---------------- scratch (static device globals; no runtime allocation) ----------------
__device__ int   g_nbr_sorted[NN * DD];
__device__ float g_P[(size_t)NN * G4];
__device__ float g_agg[(size_t)NN * HH];
__device__ float g_hbufA[(size_t)NN * HH];
__device__ float g_hbufB[(size_t)NN * HH];

// ---------------- math helpers ----------------
__device__ __forceinline__ float tanh_fast(float x) {
    float y;
    asm("tanh.approx.f32 %0, %1;" : "=f"(y) : "f"(x));
    return y;
}
__device__ __forceinline__ float sig_fast(float x) {
    return fmaf(0.5f, tanh_fast(0.5f * x), 0.5f);
}
__device__ __forceinline__ uint32_t pack2(float a, float b) {
    __half2 h = __floats2half2_rn(a, b);
    return *reinterpret_cast<uint32_t*>(&h);
}
__device__ __forceinline__ void cp_async8(uint32_t dst_smem, const void* src) {
    asm volatile("cp.async.ca.shared.global [%0], [%1], 8;" :: "r"(dst_smem), "l"(src));
}

// ---------------- 1) sort neighbors: one warp per node, bitonic-32 ----------------
__global__ void sort_nbr_kernel(const int* __restrict__ nbr) {
    int gtid = blockIdx.x * blockDim.x + threadIdx.x;
    int node = gtid >> 5;
    int lane = gtid & 31;
    if (node >= NN) return;
    int v = nbr[node * DD + lane];
#pragma unroll
    for (int k = 2; k <= 32; k <<= 1) {
#pragma unroll
        for (int j = k >> 1; j > 0; j >>= 1) {
            int p = __shfl_xor_sync(0xffffffffu, v, j);
            bool dirUp   = ((lane & k) == 0);
            bool lower   = ((lane & j) == 0);
            bool keepMin = (lower == dirUp);
            int mn = min(v, p), mx = max(v, p);
            v = keepMin ? mn : mx;
        }
    }
    g_nbr_sorted[node * DD + lane] = v;
}

// ---------------- 2) P = h_prev @ W_ih^T + (b_ih + b_hh)  [N, 256] ----------------
template <int IND>
__global__ __launch_bounds__(256) void proj_kernel(const float* __restrict__ hprev,
                                                   const float* __restrict__ W_ih,
                                                   const float* __restrict__ b_ih,
                                                   const float* __restrict__ b_hh) {
    __shared__ float hrow[16 * IND];
    const int j    = threadIdx.x;
    const int base = blockIdx.x * 16;

    float w[IND];
#pragma unroll
    for (int k = 0; k < IND; k++) w[k] = __ldg(&W_ih[j * IND + k]);
    float bias = __ldg(&b_ih[j]) + __ldg(&b_hh[j]);

    for (int e = j; e < 16 * IND; e += 256) hrow[e] = hprev[(size_t)base * IND + e];
    __syncthreads();

#pragma unroll
    for (int n0 = 0; n0 < 16; n0 += 4) {
        float acc[4] = {bias, bias, bias, bias};
#pragma unroll
        for (int k = 0; k < IND; k++) {
            float wv = w[k];
#pragma unroll
            for (int c = 0; c < 4; c++)
                acc[c] = fmaf(hrow[(n0 + c) * IND + k], wv, acc[c]);
        }
#pragma unroll
        for (int c = 0; c < 4; c++)
            g_P[(size_t)(base + n0 + c) * G4 + j] = acc[c];
    }
}

// ---------------- 3) LSTM via fp16 mma, cp.async-staged P, occ 2 ----------------
// Block: 32 nodes, 8 warps. Warp w owns hidden dims [8w,8w+8) for all 4 gates ->
// cell update register-local. W_hh B-fragments resident in regs. P[idx_t] gate
// init staged via cp.async into thread-private fragment-ordered smem (double
// buffered, LDS.128 conflict-free readback). h double-buffered in smem ->
// ONE barrier per step. kk-outer MMA keeps only 8 A-regs live.

__global__ __launch_bounds__(256, 2) void lstm_mma_kernel(const float* __restrict__ W_hh,
                                                          const float* __restrict__ P) {
    extern __shared__ char dsm[];
    char* stage  = dsm;                  // [2][8 slots][256 tid][16B]
    char* hbase  = dsm + STAGE_BYTES;    // [2][32][64] fp16, xor-swizzled

    const int tid  = threadIdx.x;
    const int w    = tid >> 5;
    const int lane = tid & 31;
    const int grp  = lane >> 2;
    const int tig  = lane & 3;
    const int base = blockIdx.x * MT;
    const int col0 = 8 * w + tig * 2;

    const uint32_t st32 = (uint32_t)__cvta_generic_to_shared(stage);
    const uint32_t hb32 = (uint32_t)__cvta_generic_to_shared(hbase);

    // ---- W_hh -> B fragments (resident) ----
    uint32_t Bfr[4][4][2];
#pragma unroll
    for (int g = 0; g < 4; g++) {
        const float* row = W_hh + (size_t)(64 * g + 8 * w + grp) * HH;
#pragma unroll
        for (int kk = 0; kk < 4; kk++) {
            const float* rk = row + kk * 16 + tig * 2;
            Bfr[g][kk][0] = pack2(__ldg(rk),     __ldg(rk + 1));
            Bfr[g][kk][1] = pack2(__ldg(rk + 8), __ldg(rk + 9));
        }
    }

    // ---- ldmatrix addresses (byte offsets + hb32; add 0/4096 buffer offset at use) ----
    uint32_t lmaddr[2][4];
    {
        int sub = lane >> 3;
#pragma unroll
        for (int m = 0; m < 2; m++)
#pragma unroll
            for (int kk = 0; kk < 4; kk++) {
                int rr   = m * 16 + (lane & 7) + (sub & 1) * 8;
                int gcol = kk * 2 + (sub >> 1);
                int pc   = (gcol ^ (rr & 7)) << 3;
                lmaddr[m][kk] = hb32 + (uint32_t)(rr * HH * 2 + pc * 2);
            }
    }
    // ---- h-store byte offsets (within one 4KB buffer) ----
    uint32_t staddr[4];
    {
        int pc = ((w ^ grp) << 3) + tig * 2;
#pragma unroll
        for (int j = 0; j < 4; j++) {
            int r = (j >> 1) * 16 + (j & 1) * 8 + grp;
            staddr[j] = (uint32_t)(r * HH * 2 + pc * 2);
        }
    }

    // ---- zero both h buffers ----
    for (int e = tid; e < 2 * MT * HH / 2; e += 256)
        reinterpret_cast<uint32_t*>(hbase)[e] = 0u;

    // ---- preloop: stage P[idx_0] into buffer 0 ----
    {
        int idxr[4];
#pragma unroll
        for (int j = 0; j < 4; j++)
            idxr[j] = g_nbr_sorted[(base + j * 8 + grp) * DD + 0];
#pragma unroll
        for (int m = 0; m < 2; m++)
#pragma unroll
            for (int g = 0; g < 4; g++) {
                uint32_t dst = st32 + (uint32_t)(((m * 4 + g) * 256 + tid) * 16);
#pragma unroll
                for (int p = 0; p < 2; p++)
                    cp_async8(dst + p * 8,
                              P + (size_t)idxr[m * 2 + p] * G4 + 64 * g + col0);
            }
        asm volatile("cp.async.commit_group;");
    }

    float cst[2][4] = {{0.f,0.f,0.f,0.f},{0.f,0.f,0.f,0.f}};

#pragma unroll 1
    for (int t = 0; t < DD; t++) {
        const int rb = ((t & 1) ^ 1) * 4096;   // read-h buffer byte offset
        const int wb = (t & 1) * 4096;         // write-h buffer byte offset
        const int sb = (t & 1) * (STAGE_BYTES / 2);   // stage buffer for this step

        // ---- 1) issue async stage for t+1 ----
        if (t < DD - 1) {
            int idxr[4];
#pragma unroll
            for (int j = 0; j < 4; j++)
                idxr[j] = g_nbr_sorted[(base + j * 8 + grp) * DD + (t + 1)];
            uint32_t sbn = st32 + (uint32_t)(((t + 1) & 1) * (STAGE_BYTES / 2));
#pragma unroll
            for (int m = 0; m < 2; m++)
#pragma unroll
                for (int g = 0; g < 4; g++) {
                    uint32_t dst = sbn + (uint32_t)(((m * 4 + g) * 256 + tid) * 16);
#pragma unroll
                    for (int p = 0; p < 2; p++)
                        cp_async8(dst + p * 8,
                                  P + (size_t)idxr[m * 2 + p] * G4 + 64 * g + col0);
                }
            asm volatile("cp.async.commit_group;");
            asm volatile("cp.async.wait_group 1;" ::: "memory");
        } else {
            asm volatile("cp.async.wait_group 0;" ::: "memory");
        }

        // ---- 2) gate init from thread-private stage (LDS.128, conflict-free) ----
        float cur[2][4][4];
#pragma unroll
        for (int m = 0; m < 2; m++)
#pragma unroll
            for (int g = 0; g < 4; g++) {
                float4 v = *reinterpret_cast<const float4*>(
                    stage + sb + ((m * 4 + g) * 256 + tid) * 16);
                cur[m][g][0] = v.x; cur[m][g][1] = v.y;
                cur[m][g][2] = v.z; cur[m][g][3] = v.w;
            }

        // ---- 3) one barrier: h(t-1) stores visible ----
        __syncthreads();

        // ---- 4) kk-outer: ldmatrix + 8 MMAs per kk ----
#pragma unroll
        for (int kk = 0; kk < 4; kk++) {
            uint32_t A0[4], A1[4];
            asm volatile("ldmatrix.sync.aligned.m8n8.x4.shared.b16 {%0,%1,%2,%3}, [%4];"
                         : "=r"(A0[0]), "=r"(A0[1]), "=r"(A0[2]), "=r"(A0[3])
                         : "r"(lmaddr[0][kk] + rb));
            asm volatile("ldmatrix.sync.aligned.m8n8.x4.shared.b16 {%0,%1,%2,%3}, [%4];"
                         : "=r"(A1[0]), "=r"(A1[1]), "=r"(A1[2]), "=r"(A1[3])
                         : "r"(lmaddr[1][kk] + rb));
#pragma unroll
            for (int g = 0; g < 4; g++) {
                asm volatile(
                    "mma.sync.aligned.m16n8k16.row.col.f32.f16.f16.f32 "
                    "{%0,%1,%2,%3}, {%4,%5,%6,%7}, {%8,%9}, {%0,%1,%2,%3};"
                    : "+f"(cur[0][g][0]), "+f"(cur[0][g][1]),
                      "+f"(cur[0][g][2]), "+f"(cur[0][g][3])
                    : "r"(A0[0]), "r"(A0[1]), "r"(A0[2]), "r"(A0[3]),
                      "r"(Bfr[g][kk][0]), "r"(Bfr[g][kk][1]));
                asm volatile(
                    "mma.sync.aligned.m16n8k16.row.col.f32.f16.f16.f32 "
                    "{%0,%1,%2,%3}, {%4,%5,%6,%7}, {%8,%9}, {%0,%1,%2,%3};"
                    : "+f"(cur[1][g][0]), "+f"(cur[1][g][1]),
                      "+f"(cur[1][g][2]), "+f"(cur[1][g][3])
                    : "r"(A1[0]), "r"(A1[1]), "r"(A1[2]), "r"(A1[3]),
                      "r"(Bfr[g][kk][0]), "r"(Bfr[g][kk][1]));
            }
        }

        // ---- 5) activations + cell update (register-local) ----
        float hv[2][4];
#pragma unroll
        for (int m = 0; m < 2; m++)
#pragma unroll
            for (int e = 0; e < 4; e++) {
                float ig = sig_fast (cur[m][0][e]);
                float fg = sig_fast (cur[m][1][e]);
                float gg = tanh_fast(cur[m][2][e]);
                float og = sig_fast (cur[m][3][e]);
                float c  = fmaf(fg, cst[m][e], ig * gg);
                cst[m][e] = c;
                hv[m][e]  = og * tanh_fast(c);
            }

        // ---- 6) store h(t) (or final agg) ----
        if (t == DD - 1) {
            const int d = 8 * w + tig * 2;
#pragma unroll
            for (int m = 0; m < 2; m++)
#pragma unroll
                for (int rh = 0; rh < 2; rh++) {
                    int r = m * 16 + rh * 8 + grp;
                    float2 v = make_float2(hv[m][rh * 2], hv[m][rh * 2 + 1]);
                    *reinterpret_cast<float2*>(&g_agg[(size_t)(base + r) * HH + d]) = v;
                }
        } else {
#pragma unroll
            for (int m = 0; m < 2; m++)
#pragma unroll
                for (int rh = 0; rh < 2; rh++) {
                    uint32_t v = pack2(hv[m][rh * 2], hv[m][rh * 2 + 1]);
                    *reinterpret_cast<uint32_t*>(hbase + wb + staddr[m * 2 + rh]) = v;
                }
        }
    }
}

// ---------------- 4) h_next = relu([h_prev | agg] @ Wl^T + bl) ----------------
template <int IND>
__global__ __launch_bounds__(256) void combine_kernel(const float* __restrict__ hprev,
                                                      const float* __restrict__ Wl,
                                                      const float* __restrict__ bl,
                                                      float* __restrict__ hnext) {
    constexpr int KD    = IND + HH;
    constexpr int PITCH = KD | 1;
    __shared__ float Wsm[HH * PITCH];
    __shared__ float xin[16][KD];

    const int t    = threadIdx.x;
    const int base = blockIdx.x * 16;

    for (int e = t; e < HH * KD; e += 256) {
        int d = e / KD, k = e - d * KD;
        Wsm[d * PITCH + k] = Wl[e];
    }
    for (int e = t; e < 16 * KD; e += 256) {
        int n = e / KD, k = e - n * KD;
        xin[n][k] = (k < IND) ? hprev[(size_t)(base + n) * IND + k]
                              : g_agg[(size_t)(base + n) * HH + (k - IND)];
    }
    __syncthreads();

    const int d = t & 63;
    int   nidx[4];
    float acc[4];
#pragma unroll
    for (int p = 0; p < 4; p++) { nidx[p] = p * 4 + (t >> 6); acc[p] = __ldg(&bl[d]); }
#pragma unroll
    for (int k = 0; k < KD; k++) {
        float wv = Wsm[d * PITCH + k];
#pragma unroll
        for (int p = 0; p < 4; p++)
            acc[p] = fmaf(xin[nidx[p]][k], wv, acc[p]);
    }
#pragma unroll
    for (int p = 0; p < 4; p++)
        hnext[(size_t)(base + nidx[p]) * HH + d] = fmaxf(acc[p], 0.0f);
}

// ---------------- 5) out[n] = h @ W_out^T + b_out ----------------
__global__ void out_kernel(const float* __restrict__ h, const float* __restrict__ Wo,
                           const float* __restrict__ bo, float* __restrict__ out) {
    int gtid = blockIdx.x * blockDim.x + threadIdx.x;
    int node = gtid >> 5;
    int lane = gtid & 31;
    if (node >= NN) return;
    const float* hr = h + (size_t)node * HH;
    float s = hr[lane] * __ldg(&Wo[lane]) + hr[32 + lane] * __ldg(&Wo[32 + lane]);
#pragma unroll
    for (int o = 16; o > 0; o >>= 1) s += __shfl_xor_sync(0xffffffffu, s, o);
    if (lane == 0) out[node] = s + __ldg(&bo[0]);
}

// ---------------- launch ----------------
extern "C" void kernel_launch(void* const* d_in, const int* in_sizes, int n_in,
                              void* d_out, int out_size) {
    const float* node_features = (const float*)d_in[0];
    const int*   nbr           = (const int*)d_in[1];
    const float* W_ih[3] = {(const float*)d_in[2],  (const float*)d_in[8],  (const float*)d_in[14]};
    const float* W_hh[3] = {(const float*)d_in[3],  (const float*)d_in[9],  (const float*)d_in[15]};
    const float* b_ih[3] = {(const float*)d_in[4],  (const float*)d_in[10], (const float*)d_in[16]};
    const float* b_hh[3] = {(const float*)d_in[5],  (const float*)d_in[11], (const float*)d_in[17]};
    const float* Wl[3]   = {(const float*)d_in[6],  (const float*)d_in[12], (const float*)d_in[18]};
    const float* bl[3]   = {(const float*)d_in[7],  (const float*)d_in[13], (const float*)d_in[19]};
    const float* W_out   = (const float*)d_in[20];
    const float* b_out   = (const float*)d_in[21];
    float* out = (float*)d_out;

    void *pA = nullptr, *pB = nullptr, *pP = nullptr;
    cudaGetSymbolAddress(&pA, g_hbufA);
    cudaGetSymbolAddress(&pB, g_hbufB);
    cudaGetSymbolAddress(&pP, g_P);
    float* hA = (float*)pA;
    float* hB = (float*)pB;
    const float* Pp = (const float*)pP;

    cudaFuncSetAttribute(lstm_mma_kernel,
                         cudaFuncAttributeMaxDynamicSharedMemorySize, LSTM_SMEM);

    const int NBLK16 = NN / 16;  // 1250

    sort_nbr_kernel<<<(NN * 32 + 255) / 256, 256>>>(nbr);

    // layer 0
    proj_kernel<3><<<NBLK16, 256>>>(node_features, W_ih[0], b_ih[0], b_hh[0]);
    lstm_mma_kernel<<<NBLK_LSTM, 256, LSTM_SMEM>>>(W_hh[0], Pp);
    combine_kernel<3><<<NBLK16, 256>>>(node_features, Wl[0], bl[0], hA);

    // layer 1
    proj_kernel<64><<<NBLK16, 256>>>(hA, W_ih[1], b_ih[1], b_hh[1]);
    lstm_mma_kernel<<<NBLK_LSTM, 256, LSTM_SMEM>>>(W_hh[1], Pp);
    combine_kernel<64><<<NBLK16, 256>>>(hA, Wl[1], bl[1], hB);

    // layer 2
    proj_kernel<64><<<NBLK16, 256>>>(hB, W_ih[2], b_ih[2], b_hh[2]);
    lstm_mma_kernel<<<NBLK_LSTM, 256, LSTM_SMEM>>>(W_hh[2], Pp);
    combine_kernel<64><<<NBLK16, 256>>>(hB, Wl[2], bl[2], hA);

    out_kernel<<<(NN * 32 + 255) / 256, 256>>>(hA, W_out, b_out, out);
}

// round 4
// speedup vs baseline: 5.4847x; 1.7640x over previous
#include <cuda_runtime.h>
#include <cuda_fp16.h>
#include <cstdint>

#define NN    20000
#define DD    32
#define HH    64
#define G4    256   // 4*H
#define MT    32    // nodes per lstm block
#define NBLK_LSTM (NN / MT)   // 625

// ---------------- scratch (static device globals; no runtime allocation) ----------------
__device__ int    g_nbr_sorted[NN * DD];
__device__ float  g_agg[(size_t)NN * HH];
__device__ float  g_hbufA[(size_t)NN * HH];
__device__ float  g_hbufB[(size_t)NN * HH];
__device__ __half g_hf16[(size_t)NN * HH];   // fp16 copy of current layer input
__device__ __half g_x0[(size_t)NN * 16];     // layer-0 features padded to 16

// ---------------- math helpers ----------------
__device__ __forceinline__ float tanh_fast(float x) {
    float y;
    asm("tanh.approx.f32 %0, %1;" : "=f"(y) : "f"(x));
    return y;
}
__device__ __forceinline__ float sig_fast(float x) {
    return fmaf(0.5f, tanh_fast(0.5f * x), 0.5f);
}
__device__ __forceinline__ uint32_t pack2(float a, float b) {
    __half2 h = __floats2half2_rn(a, b);
    return *reinterpret_cast<uint32_t*>(&h);
}
__device__ __forceinline__ void cp_async16(uint32_t dst_smem, const void* src) {
    asm volatile("cp.async.ca.shared.global [%0], [%1], 16;" :: "r"(dst_smem), "l"(src));
}

// ---------------- 1) sort neighbors: one warp per node, bitonic-32 ----------------
__global__ void sort_nbr_kernel(const int* __restrict__ nbr) {
    int gtid = blockIdx.x * blockDim.x + threadIdx.x;
    int node = gtid >> 5;
    int lane = gtid & 31;
    if (node >= NN) return;
    int v = nbr[node * DD + lane];
#pragma unroll
    for (int k = 2; k <= 32; k <<= 1) {
#pragma unroll
        for (int j = k >> 1; j > 0; j >>= 1) {
            int p = __shfl_xor_sync(0xffffffffu, v, j);
            bool dirUp   = ((lane & k) == 0);
            bool lower   = ((lane & j) == 0);
            bool keepMin = (lower == dirUp);
            int mn = min(v, p), mx = max(v, p);
            v = keepMin ? mn : mx;
        }
    }
    g_nbr_sorted[node * DD + lane] = v;
}

// ---------------- 1b) prep layer-0 x: [N,3] fp32 -> [N,16] fp16 zero-padded ----------------
__global__ void prep_x0_kernel(const float* __restrict__ nf) {
    int i = blockIdx.x * 256 + threadIdx.x;
    if (i >= NN * 16) return;
    int n = i >> 4, k = i & 15;
    g_x0[i] = __float2half(k < 3 ? nf[n * 3 + k] : 0.0f);
}

// ---------------- 2) LSTM: gates = bias + x_t@W_ih^T + h@W_hh^T, all tensor-core ----------------
// Block: 32 nodes, 8 warps. Warp w owns gate-cols [64g+8w, 64g+8w+8) for g=0..3,
// so i/f/g/o for one (node,dim) are register-local in one thread.
// x_t rows gathered as fp16 (128B or 32B per row) via cp.async into swizzled
// double-buffered smem. W_hh lives in registers as B-frags; W_ih in smem
// (n-major, pad 8 halves) read per step via ldmatrix.x2. Gate init = bias regs.
// XK = padded x width (16 or 64), XKG = true x width in gmem weights (3 or 64).

template <int XK, int XKG>
__global__ __launch_bounds__(256, 2) void lstm_mma_kernel(
    const float* __restrict__ W_hh, const float* __restrict__ W_ih,
    const float* __restrict__ b_ih, const float* __restrict__ b_hh,
    const __half* __restrict__ xsrc)
{
    extern __shared__ char dsm[];
    constexpr int XSTB   = MT * XK * 2;        // one x stage buffer (bytes)
    constexpr int HB0    = 2 * XSTB;           // h buffers start
    constexpr int WIH0   = HB0 + 8192;         // W_ih smem start
    constexpr int WPITCH = XK + 8;             // halves per W_ih row (padded)
    constexpr int KKX    = XK / 16;            // x k-tiles
    constexpr int XMASK  = (XK == 64) ? 7 : 1; // swizzle mask for x rows

    const int tid  = threadIdx.x;
    const int w    = tid >> 5;
    const int lane = tid & 31;
    const int grp  = lane >> 2;
    const int tig  = lane & 3;
    const int base = blockIdx.x * MT;
    const int col0 = 8 * w + tig * 2;

    const uint32_t sm32 = (uint32_t)__cvta_generic_to_shared(dsm);

    // ---- W_ih -> smem (n-major [256][WPITCH] fp16, zero-padded cols) ----
    {
        __half* wsm = reinterpret_cast<__half*>(dsm + WIH0);
        for (int e = tid; e < 256 * XK; e += 256) {
            int n = e / XK, k = e - n * XK;
            float v = (k < XKG) ? __ldg(&W_ih[n * XKG + k]) : 0.0f;
            wsm[n * WPITCH + k] = __float2half(v);
        }
    }

    // ---- W_hh -> B fragments (resident in regs) ----
    uint32_t Bhh[4][4][2];
#pragma unroll
    for (int g = 0; g < 4; g++) {
        const float* row = W_hh + (size_t)(64 * g + 8 * w + grp) * HH;
#pragma unroll
        for (int kk = 0; kk < 4; kk++) {
            const float* rk = row + kk * 16 + tig * 2;
            Bhh[g][kk][0] = pack2(__ldg(rk),     __ldg(rk + 1));
            Bhh[g][kk][1] = pack2(__ldg(rk + 8), __ldg(rk + 9));
        }
    }

    // ---- bias regs: gate-col = 64g + col0 + {0,1} ----
    float bias[4][2];
#pragma unroll
    for (int g = 0; g < 4; g++) {
#pragma unroll
        for (int e = 0; e < 2; e++) {
            int c = 64 * g + col0 + e;
            bias[g][e] = __ldg(&b_ih[c]) + __ldg(&b_hh[c]);
        }
    }

    // ---- ldmatrix addresses for h (stride 128B, xor-swizzle over 8 chunks) ----
    uint32_t lmh[2][4];
    {
        int sub = lane >> 3;
#pragma unroll
        for (int m = 0; m < 2; m++)
#pragma unroll
            for (int kk = 0; kk < 4; kk++) {
                int rr   = m * 16 + (lane & 7) + (sub & 1) * 8;
                int gcol = kk * 2 + (sub >> 1);
                int pc   = (gcol ^ (rr & 7));
                lmh[m][kk] = sm32 + (uint32_t)(HB0 + rr * 128 + pc * 16);
            }
    }
    // ---- ldmatrix addresses for x stage (stride XK*2 bytes) ----
    uint32_t lmx[2][KKX];
    {
        int sub = lane >> 3;
#pragma unroll
        for (int m = 0; m < 2; m++)
#pragma unroll
            for (int kk = 0; kk < KKX; kk++) {
                int rr   = m * 16 + (lane & 7) + (sub & 1) * 8;
                int gcol = kk * 2 + (sub >> 1);
                int pc   = (gcol ^ (rr & XMASK));
                lmx[m][kk] = sm32 + (uint32_t)(rr * (XK * 2) + pc * 16);
            }
    }
    // ---- W_ih ldmatrix base (per-thread row ptr; lanes 0-7 k-low, 8-15 k-high) ----
    uint32_t lmw;
    {
        int r  = lane & 7;
        int kh = (lane >> 3) & 1;
        lmw = sm32 + (uint32_t)(WIH0 + ((8 * w + r) * WPITCH + kh * 8) * 2);
    }
    // ---- h-store byte offsets ----
    uint32_t sth[4];
    {
        int pc = ((w ^ grp) << 3) + tig * 2;
#pragma unroll
        for (int j = 0; j < 4; j++) {
            int r = (j >> 1) * 16 + (j & 1) * 8 + grp;
            sth[j] = (uint32_t)(HB0 + r * 128 + pc * 2);
        }
    }

    // ---- cp.async src/dst mapping (per-thread, fixed row/chunk) ----
    const int xr = (XK == 64) ? (tid >> 3) : (tid >> 1);   // node row in tile
    const int xc = (XK == 64) ? (tid & 7)  : (tid & 1);    // 16B chunk
    const bool xact = (XK == 64) ? true : (tid < 64);
    const uint32_t xdst0 = sm32 + (uint32_t)(xr * (XK * 2) + ((xc ^ (xr & XMASK)) << 4));

    // ---- zero both h buffers ----
    for (int e = tid; e < 2 * MT * HH / 2; e += 256)
        reinterpret_cast<uint32_t*>(dsm + HB0)[e] = 0u;

    // ---- preload x stage buffer 0 ----
    if (xact) {
        int idx = __ldg(&g_nbr_sorted[(base + xr) * DD + 0]);
        cp_async16(xdst0, xsrc + (size_t)idx * XK + xc * 8);
    }
    asm volatile("cp.async.commit_group;");

    float cst[2][4] = {{0.f,0.f,0.f,0.f},{0.f,0.f,0.f,0.f}};

#pragma unroll 1
    for (int t = 0; t < DD; t++) {
        const uint32_t xrb = (uint32_t)((t & 1) * XSTB);
        const uint32_t hrb = (uint32_t)(((t & 1) ^ 1) * 4096);
        const uint32_t hwb = (uint32_t)((t & 1) * 4096);

        // stage(t) complete for this thread, then barrier -> visible to all;
        // barrier also covers h(t-1) stores and (t=0) Wih smem init.
        asm volatile("cp.async.wait_group 0;" ::: "memory");
        __syncthreads();

        // issue stage(t+1) — safe after barrier (everyone done reading that buffer)
        if (t < DD - 1 && xact) {
            int idx = __ldg(&g_nbr_sorted[(base + xr) * DD + (t + 1)]);
            cp_async16(xdst0 + ((t + 1) & 1) * XSTB,
                       xsrc + (size_t)idx * XK + xc * 8);
        }
        asm volatile("cp.async.commit_group;");

        // ---- gate init from bias regs ----
        float cur[2][4][4];
#pragma unroll
        for (int m = 0; m < 2; m++)
#pragma unroll
            for (int g = 0; g < 4; g++) {
                cur[m][g][0] = bias[g][0]; cur[m][g][1] = bias[g][1];
                cur[m][g][2] = bias[g][0]; cur[m][g][3] = bias[g][1];
            }

        // ---- x-part: gates += x_t @ W_ih^T ----
#pragma unroll
        for (int kk = 0; kk < KKX; kk++) {
            uint32_t A0[4], A1[4];
            asm volatile("ldmatrix.sync.aligned.m8n8.x4.shared.b16 {%0,%1,%2,%3}, [%4];"
                         : "=r"(A0[0]), "=r"(A0[1]), "=r"(A0[2]), "=r"(A0[3])
                         : "r"(lmx[0][kk] + xrb));
            asm volatile("ldmatrix.sync.aligned.m8n8.x4.shared.b16 {%0,%1,%2,%3}, [%4];"
                         : "=r"(A1[0]), "=r"(A1[1]), "=r"(A1[2]), "=r"(A1[3])
                         : "r"(lmx[1][kk] + xrb));
#pragma unroll
            for (int g = 0; g < 4; g++) {
                uint32_t B0, B1;
                asm volatile("ldmatrix.sync.aligned.m8n8.x2.shared.b16 {%0,%1}, [%2];"
                             : "=r"(B0), "=r"(B1)
                             : "r"(lmw + (uint32_t)((64 * g * WPITCH + kk * 16) * 2)));
                asm volatile(
                    "mma.sync.aligned.m16n8k16.row.col.f32.f16.f16.f32 "
                    "{%0,%1,%2,%3}, {%4,%5,%6,%7}, {%8,%9}, {%0,%1,%2,%3};"
                    : "+f"(cur[0][g][0]), "+f"(cur[0][g][1]),
                      "+f"(cur[0][g][2]), "+f"(cur[0][g][3])
                    : "r"(A0[0]), "r"(A0[1]), "r"(A0[2]), "r"(A0[3]),
                      "r"(B0), "r"(B1));
                asm volatile(
                    "mma.sync.aligned.m16n8k16.row.col.f32.f16.f16.f32 "
                    "{%0,%1,%2,%3}, {%4,%5,%6,%7}, {%8,%9}, {%0,%1,%2,%3};"
                    : "+f"(cur[1][g][0]), "+f"(cur[1][g][1]),
                      "+f"(cur[1][g][2]), "+f"(cur[1][g][3])
                    : "r"(A1[0]), "r"(A1[1]), "r"(A1[2]), "r"(A1[3]),
                      "r"(B0), "r"(B1));
            }
        }

        // ---- h-part: gates += h(t-1) @ W_hh^T ----
#pragma unroll
        for (int kk = 0; kk < 4; kk++) {
            uint32_t A0[4], A1[4];
            asm volatile("ldmatrix.sync.aligned.m8n8.x4.shared.b16 {%0,%1,%2,%3}, [%4];"
                         : "=r"(A0[0]), "=r"(A0[1]), "=r"(A0[2]), "=r"(A0[3])
                         : "r"(lmh[0][kk] + hrb));
            asm volatile("ldmatrix.sync.aligned.m8n8.x4.shared.b16 {%0,%1,%2,%3}, [%4];"
                         : "=r"(A1[0]), "=r"(A1[1]), "=r"(A1[2]), "=r"(A1[3])
                         : "r"(lmh[1][kk] + hrb));
#pragma unroll
            for (int g = 0; g < 4; g++) {
                asm volatile(
                    "mma.sync.aligned.m16n8k16.row.col.f32.f16.f16.f32 "
                    "{%0,%1,%2,%3}, {%4,%5,%6,%7}, {%8,%9}, {%0,%1,%2,%3};"
                    : "+f"(cur[0][g][0]), "+f"(cur[0][g][1]),
                      "+f"(cur[0][g][2]), "+f"(cur[0][g][3])
                    : "r"(A0[0]), "r"(A0[1]), "r"(A0[2]), "r"(A0[3]),
                      "r"(Bhh[g][kk][0]), "r"(Bhh[g][kk][1]));
                asm volatile(
                    "mma.sync.aligned.m16n8k16.row.col.f32.f16.f16.f32 "
                    "{%0,%1,%2,%3}, {%4,%5,%6,%7}, {%8,%9}, {%0,%1,%2,%3};"
                    : "+f"(cur[1][g][0]), "+f"(cur[1][g][1]),
                      "+f"(cur[1][g][2]), "+f"(cur[1][g][3])
                    : "r"(A1[0]), "r"(A1[1]), "r"(A1[2]), "r"(A1[3]),
                      "r"(Bhh[g][kk][0]), "r"(Bhh[g][kk][1]));
            }
        }

        // ---- activations + cell update (register-local) ----
        float hv[2][4];
#pragma unroll
        for (int m = 0; m < 2; m++)
#pragma unroll
            for (int e = 0; e < 4; e++) {
                float ig = sig_fast (cur[m][0][e]);
                float fg = sig_fast (cur[m][1][e]);
                float gg = tanh_fast(cur[m][2][e]);
                float og = sig_fast (cur[m][3][e]);
                float c  = fmaf(fg, cst[m][e], ig * gg);
                cst[m][e] = c;
                hv[m][e]  = og * tanh_fast(c);
            }

        // ---- store h(t) / final agg ----
        if (t == DD - 1) {
#pragma unroll
            for (int m = 0; m < 2; m++)
#pragma unroll
                for (int rh = 0; rh < 2; rh++) {
                    int r = m * 16 + rh * 8 + grp;
                    float2 v = make_float2(hv[m][rh * 2], hv[m][rh * 2 + 1]);
                    *reinterpret_cast<float2*>(&g_agg[(size_t)(base + r) * HH + col0]) = v;
                }
        } else {
#pragma unroll
            for (int m = 0; m < 2; m++)
#pragma unroll
                for (int rh = 0; rh < 2; rh++) {
                    uint32_t v = pack2(hv[m][rh * 2], hv[m][rh * 2 + 1]);
                    *reinterpret_cast<uint32_t*>(dsm + hwb + sth[m * 2 + rh]) = v;
                }
        }
    }
}

// ---------------- 3) h_next = relu([h_prev | agg] @ Wl^T + bl), fp32 + fp16 out ----------------
template <int IND>
__global__ __launch_bounds__(256) void combine_kernel(const float* __restrict__ hprev,
                                                      const float* __restrict__ Wl,
                                                      const float* __restrict__ bl,
                                                      float* __restrict__ hnext,
                                                      __half* __restrict__ h16) {
    constexpr int KD    = IND + HH;
    constexpr int PITCH = KD | 1;
    __shared__ float Wsm[HH * PITCH];
    __shared__ float xin[16][KD];

    const int t    = threadIdx.x;
    const int base = blockIdx.x * 16;

    for (int e = t; e < HH * KD; e += 256) {
        int d = e / KD, k = e - d * KD;
        Wsm[d * PITCH + k] = Wl[e];
    }
    for (int e = t; e < 16 * KD; e += 256) {
        int n = e / KD, k = e - n * KD;
        xin[n][k] = (k < IND) ? hprev[(size_t)(base + n) * IND + k]
                              : g_agg[(size_t)(base + n) * HH + (k - IND)];
    }
    __syncthreads();

    const int d = t & 63;
    int   nidx[4];
    float acc[4];
#pragma unroll
    for (int p = 0; p < 4; p++) { nidx[p] = p * 4 + (t >> 6); acc[p] = __ldg(&bl[d]); }
#pragma unroll
    for (int k = 0; k < KD; k++) {
        float wv = Wsm[d * PITCH + k];
#pragma unroll
        for (int p = 0; p < 4; p++)
            acc[p] = fmaf(xin[nidx[p]][k], wv, acc[p]);
    }
#pragma unroll
    for (int p = 0; p < 4; p++) {
        float v = fmaxf(acc[p], 0.0f);
        hnext[(size_t)(base + nidx[p]) * HH + d] = v;
        h16  [(size_t)(base + nidx[p]) * HH + d] = __float2half(v);
    }
}

// ---------------- 4) out[n] = h @ W_out^T + b_out ----------------
__global__ void out_kernel(const float* __restrict__ h, const float* __restrict__ Wo,
                           const float* __restrict__ bo, float* __restrict__ out) {
    int gtid = blockIdx.x * blockDim.x + threadIdx.x;
    int node = gtid >> 5;
    int lane = gtid & 31;
    if (node >= NN) return;
    const float* hr = h + (size_t)node * HH;
    float s = hr[lane] * __ldg(&Wo[lane]) + hr[32 + lane] * __ldg(&Wo[32 + lane]);
#pragma unroll
    for (int o = 16; o > 0; o >>= 1) s += __shfl_xor_sync(0xffffffffu, s, o);
    if (lane == 0) out[node] = s + __ldg(&bo[0]);
}

// ---------------- launch ----------------
extern "C" void kernel_launch(void* const* d_in, const int* in_sizes, int n_in,
                              void* d_out, int out_size) {
    const float* node_features = (const float*)d_in[0];
    const int*   nbr           = (const int*)d_in[1];
    const float* W_ih[3] = {(const float*)d_in[2],  (const float*)d_in[8],  (const float*)d_in[14]};
    const float* W_hh[3] = {(const float*)d_in[3],  (const float*)d_in[9],  (const float*)d_in[15]};
    const float* b_ih[3] = {(const float*)d_in[4],  (const float*)d_in[10], (const float*)d_in[16]};
    const float* b_hh[3] = {(const float*)d_in[5],  (const float*)d_in[11], (const float*)d_in[17]};
    const float* Wl[3]   = {(const float*)d_in[6],  (const float*)d_in[12], (const float*)d_in[18]};
    const float* bl[3]   = {(const float*)d_in[7],  (const float*)d_in[13], (const float*)d_in[19]};
    const float* W_out   = (const float*)d_in[20];
    const float* b_out   = (const float*)d_in[21];
    float* out = (float*)d_out;

    void *pA, *pB, *pH16, *pX0;
    cudaGetSymbolAddress(&pA, g_hbufA);
    cudaGetSymbolAddress(&pB, g_hbufB);
    cudaGetSymbolAddress(&pH16, g_hf16);
    cudaGetSymbolAddress(&pX0, g_x0);
    float*  hA  = (float*)pA;
    float*  hB  = (float*)pB;
    __half* h16 = (__half*)pH16;
    __half* x0  = (__half*)pX0;

    constexpr int SMEM16 = 2*(MT*16*2) + 8192 + 256*(16+8)*2;  // 2048+8192+12288 = 22528
    constexpr int SMEM64 = 2*(MT*64*2) + 8192 + 256*(64+8)*2;  // 8192+8192+36864 = 53248
    cudaFuncSetAttribute((const void*)lstm_mma_kernel<16,3>,
                         cudaFuncAttributeMaxDynamicSharedMemorySize, SMEM16);
    cudaFuncSetAttribute((const void*)lstm_mma_kernel<64,64>,
                         cudaFuncAttributeMaxDynamicSharedMemorySize, SMEM64);

    const int NBLK16 = NN / 16;  // 1250

    sort_nbr_kernel<<<(NN * 32 + 255) / 256, 256>>>(nbr);
    prep_x0_kernel<<<(NN * 16 + 255) / 256, 256>>>(node_features);

    // layer 0
    lstm_mma_kernel<16,3><<<NBLK_LSTM, 256, SMEM16>>>(W_hh[0], W_ih[0], b_ih[0], b_hh[0], x0);
    combine_kernel<3><<<NBLK16, 256>>>(node_features, Wl[0], bl[0], hA, h16);

    // layer 1
    lstm_mma_kernel<64,64><<<NBLK_LSTM, 256, SMEM64>>>(W_hh[1], W_ih[1], b_ih[1], b_hh[1], h16);
    combine_kernel<64><<<NBLK16, 256>>>(hA, Wl[1], bl[1], hB, h16);

    // layer 2
    lstm_mma_kernel<64,64><<<NBLK_LSTM, 256, SMEM64>>>(W_hh[2], W_ih[2], b_ih[2], b_hh[2], h16);
    combine_kernel<64><<<NBLK16, 256>>>(hB, Wl[2], bl[2], hA, h16);

    out_kernel<<<(NN * 32 + 255) / 256, 256>>>(hA, W_out, b_out, out);
}